// round 1
// baseline (speedup 1.0000x reference)
#include <cuda_runtime.h>
#include <math.h>
#include <stdint.h>

#define NN 100000
#define NE 1600000

// ---------------- scratch (device globals; no allocation allowed) ----------
__device__ float g_A[NN * 128];   // transformed features t = h @ W
__device__ float g_B[NN * 128];   // h1
__device__ float g_C[NN * 128];   // residual / h
__device__ float g_asrc[NN];
__device__ float g_adst[NN];
__device__ int   g_counts[NN];
__device__ int   g_incl[NN];
__device__ int   g_rowptr[NN + 1];
__device__ int   g_cursor[NN];
__device__ int   g_csrc[NE];
__device__ float g_s2[NE];
__device__ float g_smu[NE];
__device__ float g_sls[NE];
__device__ int   g_bsums[256];
__device__ float g_wvec[3][16];

// ---------------- small utils ---------------------------------------------
__device__ __forceinline__ float warp_max(float v) {
    #pragma unroll
    for (int o = 16; o; o >>= 1) v = fmaxf(v, __shfl_xor_sync(0xffffffffu, v, o));
    return v;
}
__device__ __forceinline__ float warp_sum(float v) {
    #pragma unroll
    for (int o = 16; o; o >>= 1) v += __shfl_xor_sync(0xffffffffu, v, o);
    return v;
}
__device__ __forceinline__ float lrelu(float a) { return a > 0.f ? a : 0.2f * a; }

// ---------------- CSR build -------------------------------------------------
__global__ void zero_counts_k() {
    int i = blockIdx.x * blockDim.x + threadIdx.x;
    if (i < NN) g_counts[i] = 0;
}

__global__ void count_k(const int* __restrict__ dst) {
    int e = blockIdx.x * blockDim.x + threadIdx.x;
    if (e < NE) atomicAdd(&g_counts[dst[e]], 1);
}

__global__ void scan1_k() {
    __shared__ int sh[1024];
    int i = blockIdx.x * 1024 + threadIdx.x;
    int v = (i < NN) ? g_counts[i] : 0;
    sh[threadIdx.x] = v;
    #pragma unroll
    for (int off = 1; off < 1024; off <<= 1) {
        __syncthreads();
        int t = (threadIdx.x >= off) ? sh[threadIdx.x - off] : 0;
        __syncthreads();
        sh[threadIdx.x] += t;
    }
    __syncthreads();
    if (i < NN) g_incl[i] = sh[threadIdx.x];
    if (threadIdx.x == 1023) g_bsums[blockIdx.x] = sh[1023];
}

__global__ void scan2_k(int nb) {
    __shared__ int sh[128];
    int v = (threadIdx.x < nb) ? g_bsums[threadIdx.x] : 0;
    sh[threadIdx.x] = v;
    #pragma unroll
    for (int off = 1; off < 128; off <<= 1) {
        __syncthreads();
        int t = (threadIdx.x >= off) ? sh[threadIdx.x - off] : 0;
        __syncthreads();
        sh[threadIdx.x] += t;
    }
    __syncthreads();
    g_bsums[threadIdx.x] = sh[threadIdx.x];
}

__global__ void scan3_k() {
    int i = blockIdx.x * blockDim.x + threadIdx.x;
    if (i < NN) {
        int b = i >> 10;
        int base = (b > 0) ? g_bsums[b - 1] : 0;
        int excl = base + g_incl[i] - g_counts[i];
        g_rowptr[i] = excl;
        g_cursor[i] = excl;
    }
    if (i == 0) g_rowptr[NN] = NE;
}

// w = We[16,K] @ ae[K]  -> g_wvec[which][16]
__global__ void wvec_k(const float* __restrict__ We, const float* __restrict__ ae,
                       int K, int which) {
    int w = threadIdx.x >> 5, lane = threadIdx.x & 31;
    if (w < 16) {
        float p = 0.f;
        for (int k = lane; k < K; k += 32) p += We[w * K + k] * ae[k];
        p = warp_sum(p);
        if (lane == 0) g_wvec[which][w] = p;
    }
}

// scatter edges into CSR order, fusing the three per-edge attr scalars
__global__ void scatter_k(const int* __restrict__ src, const int* __restrict__ dst,
                          const float* __restrict__ ea) {
    __shared__ float wv[48];
    if (threadIdx.x < 48) wv[threadIdx.x] = (&g_wvec[0][0])[threadIdx.x];
    __syncthreads();
    int e = blockIdx.x * blockDim.x + threadIdx.x;
    if (e >= NE) return;
    const float4* ap = (const float4*)(ea + (size_t)e * 16);
    float av[16];
    float4 q;
    q = ap[0]; av[0] = q.x; av[1] = q.y; av[2] = q.z; av[3] = q.w;
    q = ap[1]; av[4] = q.x; av[5] = q.y; av[6] = q.z; av[7] = q.w;
    q = ap[2]; av[8] = q.x; av[9] = q.y; av[10] = q.z; av[11] = q.w;
    q = ap[3]; av[12] = q.x; av[13] = q.y; av[14] = q.z; av[15] = q.w;
    float s2 = 0.f, smu = 0.f, sls = 0.f;
    #pragma unroll
    for (int j = 0; j < 16; j++) {
        s2  += av[j] * wv[j];
        smu += av[j] * wv[16 + j];
        sls += av[j] * wv[32 + j];
    }
    int d = dst[e];
    int pos = atomicAdd(&g_cursor[d], 1);
    g_csrc[pos] = src[e];
    g_s2[pos] = s2;
    g_smu[pos] = smu;
    g_sls[pos] = sls;
}

// ---------------- GEMM: out[N,CN] = A[N,128] @ W[128,CN] (+bias) -----------
template <int CN>
__global__ void __launch_bounds__(256) gemm_k(const float* __restrict__ A,
                                              const float* __restrict__ W,
                                              const float* __restrict__ bias,
                                              float* __restrict__ out) {
    constexpr int TM = 8192 / CN;      // 64 (CN=128) or 128 (CN=64)
    extern __shared__ float sm[];
    float* Ws = sm;                    // [128][CN]
    float* As = sm + 128 * CN;         // [128][TM] (transposed)
    const int tid = threadIdx.x;
    const int m0 = blockIdx.x * TM;

    // load W (full, 128 x CN)
    constexpr int WCNT = 128 * CN / 4;
    const float4* Wg = (const float4*)W;
    float4* Ws4 = (float4*)Ws;
    #pragma unroll
    for (int i = tid; i < WCNT; i += 256) Ws4[i] = Wg[i];

    // load A tile transposed: As[k][row]
    constexpr int ACNT = TM * 128 / 4;
    for (int i = tid; i < ACNT; i += 256) {
        int row = i >> 5;              // 32 float4 per 128-wide row
        int kk = (i & 31) * 4;
        float4 v = make_float4(0.f, 0.f, 0.f, 0.f);
        int gr = m0 + row;
        if (gr < NN) v = *(const float4*)&A[(size_t)gr * 128 + kk];
        As[(kk + 0) * TM + row] = v.x;
        As[(kk + 1) * TM + row] = v.y;
        As[(kk + 2) * TM + row] = v.z;
        As[(kk + 3) * TM + row] = v.w;
    }
    __syncthreads();

    constexpr int CG = CN / 4;
    const int colg = tid % CG, rowg = tid / CG;
    const int c0 = colg * 4, r0 = rowg * 8;

    float acc[8][4];
    #pragma unroll
    for (int r = 0; r < 8; r++)
        #pragma unroll
        for (int c = 0; c < 4; c++) acc[r][c] = 0.f;

    #pragma unroll 4
    for (int k = 0; k < 128; k++) {
        float4 wv = *(const float4*)&Ws[k * CN + c0];
        float4 a0 = *(const float4*)&As[k * TM + r0];
        float4 a1 = *(const float4*)&As[k * TM + r0 + 4];
        float ar[8] = {a0.x, a0.y, a0.z, a0.w, a1.x, a1.y, a1.z, a1.w};
        #pragma unroll
        for (int r = 0; r < 8; r++) {
            acc[r][0] += ar[r] * wv.x;
            acc[r][1] += ar[r] * wv.y;
            acc[r][2] += ar[r] * wv.z;
            acc[r][3] += ar[r] * wv.w;
        }
    }

    float4 bv = make_float4(0.f, 0.f, 0.f, 0.f);
    if (bias) bv = *(const float4*)&bias[c0];
    #pragma unroll
    for (int r = 0; r < 8; r++) {
        int gr = m0 + r0 + r;
        if (gr < NN) {
            float4 o;
            o.x = acc[r][0] + bv.x;
            o.y = acc[r][1] + bv.y;
            o.z = acc[r][2] + bv.z;
            o.w = acc[r][3] + bv.w;
            *(float4*)&out[(size_t)gr * CN + c0] = o;
        }
    }
}

// ---------------- attention coefficients -----------------------------------
template <int C>
__global__ void attn_k(const float* __restrict__ t, const float* __restrict__ avs,
                       const float* __restrict__ avd) {
    int wid = (blockIdx.x * blockDim.x + threadIdx.x) >> 5;
    int lane = threadIdx.x & 31;
    if (wid >= NN) return;
    float ps = 0.f, pd = 0.f;
    #pragma unroll
    for (int c = lane; c < C; c += 32) {
        float v = t[(size_t)wid * C + c];
        ps += v * avs[c];
        pd += v * avd[c];
    }
    ps = warp_sum(ps);
    pd = warp_sum(pd);
    if (lane == 0) { g_asrc[wid] = ps; g_adst[wid] = pd; }
}

// ---------------- GAT aggregation: one warp per destination node -----------
template <int C, bool USE_S, bool RELU, bool RESID>
__global__ void agg_k(const float* __restrict__ t, const float* __restrict__ sarr,
                      const float* __restrict__ bias, const float* __restrict__ resid,
                      float* __restrict__ out) {
    constexpr int V = C / 32;
    int n = (blockIdx.x * blockDim.x + threadIdx.x) >> 5;
    int lane = threadIdx.x & 31;
    if (n >= NN) return;
    int beg = g_rowptr[n], end = g_rowptr[n + 1];
    float adstn = g_adst[n];

    // pass A: max of leaky alphas (+ sum of raw edge scalars for self-loop mean)
    float m = -1e30f, ss = 0.f;
    for (int i = beg + lane; i < end; i += 32) {
        float s = USE_S ? sarr[i] : 0.f;
        float a = lrelu(g_asrc[g_csrc[i]] + adstn + s);
        m = fmaxf(m, a);
        if (USE_S) ss += s;
    }
    m = warp_max(m);
    if (USE_S) ss = warp_sum(ss);
    int deg = end - beg;
    float aself = g_asrc[n] + adstn + (USE_S ? ss / (float)(deg > 0 ? deg : 1) : 0.f);
    aself = lrelu(aself);
    m = fmaxf(m, aself);

    // pass B: weighted gather (all lanes walk edges together, lanes = columns)
    float acc[V];
    #pragma unroll
    for (int v = 0; v < V; v++) acc[v] = 0.f;
    float denom = 0.f;
    const int cbase = lane * V;
    for (int i = beg; i < end; i++) {
        int s = g_csrc[i];
        float a = lrelu(g_asrc[s] + adstn + (USE_S ? sarr[i] : 0.f));
        float w = __expf(a - m);
        denom += w;
        float hv[V];
        if constexpr (V == 4) {
            float4 q = *(const float4*)&t[(size_t)s * C + cbase];
            hv[0] = q.x; hv[1] = q.y; hv[2] = q.z; hv[3] = q.w;
        } else {
            float2 q = *(const float2*)&t[(size_t)s * C + cbase];
            hv[0] = q.x; hv[1] = q.y;
        }
        #pragma unroll
        for (int v = 0; v < V; v++) acc[v] += w * hv[v];
    }
    // self loop
    {
        float w = __expf(aself - m);
        denom += w;
        float hv[V];
        if constexpr (V == 4) {
            float4 q = *(const float4*)&t[(size_t)n * C + cbase];
            hv[0] = q.x; hv[1] = q.y; hv[2] = q.z; hv[3] = q.w;
        } else {
            float2 q = *(const float2*)&t[(size_t)n * C + cbase];
            hv[0] = q.x; hv[1] = q.y;
        }
        #pragma unroll
        for (int v = 0; v < V; v++) acc[v] += w * hv[v];
    }

    float inv = 1.f / (denom + 1e-16f);
    float bv[V];
    if constexpr (V == 4) {
        float4 q = *(const float4*)&bias[cbase];
        bv[0] = q.x; bv[1] = q.y; bv[2] = q.z; bv[3] = q.w;
    } else {
        float2 q = *(const float2*)&bias[cbase];
        bv[0] = q.x; bv[1] = q.y;
    }
    float ov[V];
    #pragma unroll
    for (int v = 0; v < V; v++) {
        float val = acc[v] * inv + bv[v];
        if (RELU) val = fmaxf(val, 0.f);
        if (RESID) val += resid[(size_t)n * C + cbase + v];
        ov[v] = val;
    }
    if constexpr (V == 4) {
        *(float4*)&out[(size_t)n * C + cbase] = make_float4(ov[0], ov[1], ov[2], ov[3]);
    } else {
        *(float2*)&out[(size_t)n * C + cbase] = make_float2(ov[0], ov[1]);
    }
}

// ---------------- launch ----------------------------------------------------
extern "C" void kernel_launch(void* const* d_in, const int* in_sizes, int n_in,
                              void* d_out, int out_size) {
    const float* x     = (const float*)d_in[0];
    const int*   ei    = (const int*)d_in[1];
    const int*   src   = ei;
    const int*   dst   = ei + NE;
    const float* eattr = (const float*)d_in[2];
    const float* W1    = (const float*)d_in[3];
    const float* a1s   = (const float*)d_in[4];
    const float* a1d   = (const float*)d_in[5];
    const float* b1    = (const float*)d_in[6];
    const float* W2    = (const float*)d_in[7];
    const float* a2s   = (const float*)d_in[8];
    const float* a2d   = (const float*)d_in[9];
    const float* b2    = (const float*)d_in[10];
    const float* We2   = (const float*)d_in[11];
    const float* ae2   = (const float*)d_in[12];
    const float* Wr    = (const float*)d_in[13];
    const float* br    = (const float*)d_in[14];
    const float* Wmu   = (const float*)d_in[15];
    const float* amus  = (const float*)d_in[16];
    const float* amud  = (const float*)d_in[17];
    const float* bmu   = (const float*)d_in[18];
    const float* Wemu  = (const float*)d_in[19];
    const float* aemu  = (const float*)d_in[20];
    const float* Wls   = (const float*)d_in[21];
    const float* alss  = (const float*)d_in[22];
    const float* alsd  = (const float*)d_in[23];
    const float* bls   = (const float*)d_in[24];
    const float* Wels  = (const float*)d_in[25];
    const float* aels  = (const float*)d_in[26];
    float* out = (float*)d_out;

    float *A_, *B_, *C_, *s2_, *smu_, *sls_;
    cudaGetSymbolAddress((void**)&A_, g_A);
    cudaGetSymbolAddress((void**)&B_, g_B);
    cudaGetSymbolAddress((void**)&C_, g_C);
    cudaGetSymbolAddress((void**)&s2_, g_s2);
    cudaGetSymbolAddress((void**)&smu_, g_smu);
    cudaGetSymbolAddress((void**)&sls_, g_sls);

    const int SMEM = 98304;
    cudaFuncSetAttribute(gemm_k<128>, cudaFuncAttributeMaxDynamicSharedMemorySize, SMEM);
    cudaFuncSetAttribute(gemm_k<64>,  cudaFuncAttributeMaxDynamicSharedMemorySize, SMEM);

    const int NB_SCAN = (NN + 1023) / 1024;       // 98
    const int GRID_N  = (NN + 255) / 256;
    const int GRID_E  = (NE + 255) / 256;
    const int GRID_W  = 12500;                    // N warps, 8 warps/block

    // CSR build + per-edge attention scalars
    zero_counts_k<<<GRID_N, 256>>>();
    count_k<<<GRID_E, 256>>>(dst);
    scan1_k<<<NB_SCAN, 1024>>>();
    scan2_k<<<1, 128>>>(NB_SCAN);
    scan3_k<<<GRID_N, 256>>>();
    wvec_k<<<1, 512>>>(We2, ae2, 128, 0);
    wvec_k<<<1, 512>>>(Wemu, aemu, 64, 1);
    wvec_k<<<1, 512>>>(Wels, aels, 64, 2);
    scatter_k<<<GRID_E, 256>>>(src, dst, eattr);

    // conv1: h1 = relu(gat(x))
    gemm_k<128><<<(NN + 63) / 64, 256, SMEM>>>(x, W1, nullptr, A_);
    attn_k<128><<<GRID_W, 256>>>(A_, a1s, a1d);
    agg_k<128, false, true, false><<<GRID_W, 256>>>(A_, nullptr, b1, nullptr, B_);

    // residual r = x @ Wr + br
    gemm_k<128><<<(NN + 63) / 64, 256, SMEM>>>(x, Wr, br, C_);

    // conv2: h = relu(gat(h1, edge_attr)) + r
    gemm_k<128><<<(NN + 63) / 64, 256, SMEM>>>(B_, W2, nullptr, A_);
    attn_k<128><<<GRID_W, 256>>>(A_, a2s, a2d);
    agg_k<128, true, true, true><<<GRID_W, 256>>>(A_, s2_, b2, C_, C_);

    // conv_mu -> out[0 : N*64)
    gemm_k<64><<<(NN + 127) / 128, 256, SMEM>>>(C_, Wmu, nullptr, A_);
    attn_k<64><<<GRID_W, 256>>>(A_, amus, amud);
    agg_k<64, true, false, false><<<GRID_W, 256>>>(A_, smu_, bmu, nullptr, out);

    // conv_logstd -> out[N*64 : 2*N*64)
    gemm_k<64><<<(NN + 127) / 128, 256, SMEM>>>(C_, Wls, nullptr, A_);
    attn_k<64><<<GRID_W, 256>>>(A_, alss, alsd);
    agg_k<64, true, false, false><<<GRID_W, 256>>>(A_, sls_, bls, nullptr, out + (size_t)NN * 64);
}

// round 5
// speedup vs baseline: 1.3457x; 1.3457x over previous
#include <cuda_runtime.h>
#include <math.h>
#include <stdint.h>

#define NN 100000
#define NE 1600000

// ---------------- scratch (device globals) ---------------------------------
__device__ float  g_A[NN * 128];
__device__ float  g_B[NN * 128];
__device__ float  g_C[NN * 128];
__device__ float4 g_attn[NN];
__device__ int    g_counts[NN];
__device__ int    g_incl[NN];
__device__ int    g_rowptr[NN + 1];
__device__ int    g_cursor[NN];
__device__ float4 g_pack[NE];
__device__ int    g_bsums[256];
__device__ float  g_wvec[3][16];

// ---------------- helpers ---------------------------------------------------
__device__ __forceinline__ float warp_sum(float v) {
    #pragma unroll
    for (int o = 16; o; o >>= 1) v += __shfl_xor_sync(0xffffffffu, v, o);
    return v;
}
__device__ __forceinline__ float lrelu(float a) { return a > 0.f ? a : 0.2f * a; }

__device__ __forceinline__ uint32_t f2tf32(float x) {
    uint32_t r;
    asm("cvt.rna.tf32.f32 %0, %1;" : "=r"(r) : "f"(x));
    return r;
}
__device__ __forceinline__ void mma_tf32(float* c, uint32_t a0, uint32_t a1, uint32_t a2, uint32_t a3,
                                         uint32_t b0, uint32_t b1) {
    asm volatile(
        "mma.sync.aligned.m16n8k8.row.col.f32.tf32.tf32.f32 "
        "{%0,%1,%2,%3}, {%4,%5,%6,%7}, {%8,%9}, {%0,%1,%2,%3};"
        : "+f"(c[0]), "+f"(c[1]), "+f"(c[2]), "+f"(c[3])
        : "r"(a0), "r"(a1), "r"(a2), "r"(a3), "r"(b0), "r"(b1));
}

// ---------------- CSR build -------------------------------------------------
__global__ void zero_counts_k() {
    int i = blockIdx.x * blockDim.x + threadIdx.x;
    if (i < NN) g_counts[i] = 0;
}
__global__ void count_k(const int* __restrict__ dst) {
    int e = blockIdx.x * blockDim.x + threadIdx.x;
    if (e < NE) atomicAdd(&g_counts[dst[e]], 1);
}
__global__ void scan1_k() {
    __shared__ int sh[1024];
    int i = blockIdx.x * 1024 + threadIdx.x;
    int v = (i < NN) ? g_counts[i] : 0;
    sh[threadIdx.x] = v;
    #pragma unroll
    for (int off = 1; off < 1024; off <<= 1) {
        __syncthreads();
        int t = (threadIdx.x >= off) ? sh[threadIdx.x - off] : 0;
        __syncthreads();
        sh[threadIdx.x] += t;
    }
    __syncthreads();
    if (i < NN) g_incl[i] = sh[threadIdx.x];
    if (threadIdx.x == 1023) g_bsums[blockIdx.x] = sh[1023];
}
__global__ void scan2_k(int nb) {
    __shared__ int sh[128];
    int v = (threadIdx.x < nb) ? g_bsums[threadIdx.x] : 0;
    sh[threadIdx.x] = v;
    #pragma unroll
    for (int off = 1; off < 128; off <<= 1) {
        __syncthreads();
        int t = (threadIdx.x >= off) ? sh[threadIdx.x - off] : 0;
        __syncthreads();
        sh[threadIdx.x] += t;
    }
    __syncthreads();
    g_bsums[threadIdx.x] = sh[threadIdx.x];
}
__global__ void scan3_k() {
    int i = blockIdx.x * blockDim.x + threadIdx.x;
    if (i < NN) {
        int b = i >> 10;
        int base = (b > 0) ? g_bsums[b - 1] : 0;
        int excl = base + g_incl[i] - g_counts[i];
        g_rowptr[i] = excl;
        g_cursor[i] = excl;
    }
    if (i == 0) g_rowptr[NN] = NE;
}

__global__ void wvec_k(const float* __restrict__ We, const float* __restrict__ ae,
                       int K, int which) {
    int w = threadIdx.x >> 5, lane = threadIdx.x & 31;
    if (w < 16) {
        float p = 0.f;
        for (int k = lane; k < K; k += 32) p += We[w * K + k] * ae[k];
        p = warp_sum(p);
        if (lane == 0) g_wvec[which][w] = p;
    }
}

__global__ void scatter_k(const int* __restrict__ src, const int* __restrict__ dst,
                          const float* __restrict__ ea) {
    __shared__ float wv[48];
    if (threadIdx.x < 48) wv[threadIdx.x] = (&g_wvec[0][0])[threadIdx.x];
    __syncthreads();
    int e = blockIdx.x * blockDim.x + threadIdx.x;
    if (e >= NE) return;
    const float4* ap = (const float4*)(ea + (size_t)e * 16);
    float av[16];
    float4 q;
    q = ap[0]; av[0] = q.x; av[1] = q.y; av[2] = q.z; av[3] = q.w;
    q = ap[1]; av[4] = q.x; av[5] = q.y; av[6] = q.z; av[7] = q.w;
    q = ap[2]; av[8] = q.x; av[9] = q.y; av[10] = q.z; av[11] = q.w;
    q = ap[3]; av[12] = q.x; av[13] = q.y; av[14] = q.z; av[15] = q.w;
    float s2 = 0.f, smu = 0.f, sls = 0.f;
    #pragma unroll
    for (int j = 0; j < 16; j++) {
        s2  += av[j] * wv[j];
        smu += av[j] * wv[16 + j];
        sls += av[j] * wv[32 + j];
    }
    int d = dst[e];
    int pos = atomicAdd(&g_cursor[d], 1);
    g_pack[pos] = make_float4(__int_as_float(src[e]), s2, smu, sls);
}

// ---------------- 3xTF32 mma.sync GEMM + fused attention epilogue ----------
// MODE 0: out = A@W0 + bias
// MODE 1: out = A@W0, attn (ps,pd)
// MODE 2: out = A@[W0|W1], attn per 64-col half (ps0,pd0,ps1,pd1)
// tile 128x128, K=128; 8 warps: warpM in {0,1} (64 rows), warpN in {0..3} (32 cols)
#define AS_PITCH 132
#define WS_PITCH 136
#define AS_OFF   0
#define WS_OFF   (128 * AS_PITCH)                 // 16896
#define RED_OFF  (WS_OFF + 128 * WS_PITCH)        // 34304 (512 floats)
#define AV_OFF   (RED_OFF + 512)                  // 34816 (256 floats)
#define SM_FLOATS (AV_OFF + 256)                  // 35072 -> 140288 B

template <int MODE>
__global__ void __launch_bounds__(256) gemm_mma(
    const float* __restrict__ A, const float* __restrict__ W0, const float* __restrict__ W1,
    const float* __restrict__ bias,
    const float* __restrict__ avs0, const float* __restrict__ avd0,
    const float* __restrict__ avs1, const float* __restrict__ avd1,
    float* __restrict__ out, float4* __restrict__ attn_out)
{
    extern __shared__ float sm[];
    float* As = sm + AS_OFF;
    float* Ws = sm + WS_OFF;
    float* red = sm + RED_OFF;   // ps0[128] pd0[128] ps1[128] pd1[128]
    float* av  = sm + AV_OFF;    // avs[128] avd[128]

    const int tid = threadIdx.x, wid = tid >> 5, lane = tid & 31;
    const int m0 = blockIdx.x * 128;

    // ---- stage A tile [128 rows][128 k], pitch 132
    #pragma unroll
    for (int it = 0; it < 16; it++) {
        int i = tid + it * 256;
        int row = i >> 5, k4 = (i & 31) << 2;
        int gr = m0 + row;
        float4 v = make_float4(0.f, 0.f, 0.f, 0.f);
        if (gr < NN) v = *(const float4*)(A + (size_t)gr * 128 + k4);
        *(float4*)(As + row * AS_PITCH + k4) = v;
    }
    // ---- stage W [128 k][128 n], pitch 136
    #pragma unroll
    for (int it = 0; it < 16; it++) {
        int i = tid + it * 256;
        int k = i >> 5, n4 = (i & 31) << 2;
        float4 v;
        if (MODE == 2) {
            v = (n4 < 64) ? *(const float4*)(W0 + (size_t)k * 64 + n4)
                          : *(const float4*)(W1 + (size_t)k * 64 + (n4 - 64));
        } else {
            v = *(const float4*)(W0 + (size_t)k * 128 + n4);
        }
        *(float4*)(Ws + k * WS_PITCH + n4) = v;
    }
    if (MODE >= 1) {
        for (int i = tid; i < 512; i += 256) red[i] = 0.f;   // full 512-float clear
        if (tid < 128) {
            if (MODE == 1) { av[tid] = avs0[tid]; av[128 + tid] = avd0[tid]; }
            else {
                av[tid]       = (tid < 64) ? avs0[tid] : avs1[tid - 64];
                av[128 + tid] = (tid < 64) ? avd0[tid] : avd1[tid - 64];
            }
        }
    }
    __syncthreads();

    const int warpM = wid & 1, warpN = wid >> 1;
    const int RM = warpM * 64, CB = warpN * 32;
    const int r_low = lane >> 2;          // 0..7
    const int kq = lane & 3;              // 0..3
    const int cpair = kq * 2;

    float acc[4][4][4];
    #pragma unroll
    for (int mi = 0; mi < 4; mi++)
        #pragma unroll
        for (int ni = 0; ni < 4; ni++)
            #pragma unroll
            for (int r = 0; r < 4; r++) acc[mi][ni][r] = 0.f;

    #pragma unroll
    for (int ks = 0; ks < 16; ks++) {
        const int kb = ks * 8;
        uint32_t ah[4][4], al[4][4];
        #pragma unroll
        for (int mi = 0; mi < 4; mi++) {
            const float* ap = As + (RM + mi * 16 + r_low) * AS_PITCH + kb + kq;
            float x0 = ap[0];
            float x1 = ap[8 * AS_PITCH];
            float x2 = ap[4];
            float x3 = ap[8 * AS_PITCH + 4];
            ah[mi][0] = f2tf32(x0); al[mi][0] = f2tf32(x0 - __uint_as_float(ah[mi][0]));
            ah[mi][1] = f2tf32(x1); al[mi][1] = f2tf32(x1 - __uint_as_float(ah[mi][1]));
            ah[mi][2] = f2tf32(x2); al[mi][2] = f2tf32(x2 - __uint_as_float(ah[mi][2]));
            ah[mi][3] = f2tf32(x3); al[mi][3] = f2tf32(x3 - __uint_as_float(ah[mi][3]));
        }
        uint32_t bh[4][2], bl[4][2];
        #pragma unroll
        for (int ni = 0; ni < 4; ni++) {
            const float* bp = Ws + (kb + kq) * WS_PITCH + CB + ni * 8 + r_low;
            float y0 = bp[0];
            float y1 = bp[4 * WS_PITCH];
            bh[ni][0] = f2tf32(y0); bl[ni][0] = f2tf32(y0 - __uint_as_float(bh[ni][0]));
            bh[ni][1] = f2tf32(y1); bl[ni][1] = f2tf32(y1 - __uint_as_float(bh[ni][1]));
        }
        #pragma unroll
        for (int mi = 0; mi < 4; mi++)
            #pragma unroll
            for (int ni = 0; ni < 4; ni++) {
                mma_tf32(acc[mi][ni], ah[mi][0], ah[mi][1], ah[mi][2], ah[mi][3], bh[ni][0], bh[ni][1]);
                mma_tf32(acc[mi][ni], ah[mi][0], ah[mi][1], ah[mi][2], ah[mi][3], bl[ni][0], bl[ni][1]);
                mma_tf32(acc[mi][ni], al[mi][0], al[mi][1], al[mi][2], al[mi][3], bh[ni][0], bh[ni][1]);
            }
    }

    // ---- epilogue: store + fused attention dots
    const int half = (MODE == 2) ? (warpN >> 1) : 0;
    #pragma unroll
    for (int mi = 0; mi < 4; mi++) {
        int gr0 = m0 + RM + mi * 16 + r_low;
        int gr1 = gr0 + 8;
        float pA = 0.f, pB = 0.f, qA = 0.f, qB = 0.f;
        #pragma unroll
        for (int ni = 0; ni < 4; ni++) {
            int gc = CB + ni * 8 + cpair;
            float c0 = acc[mi][ni][0], c1 = acc[mi][ni][1];
            float c2 = acc[mi][ni][2], c3 = acc[mi][ni][3];
            if (MODE == 0) {
                float b0v = __ldg(bias + gc), b1v = __ldg(bias + gc + 1);
                c0 += b0v; c1 += b1v; c2 += b0v; c3 += b1v;
            } else {
                float s0 = av[gc], s1 = av[gc + 1];
                float d0 = av[128 + gc], d1 = av[128 + gc + 1];
                pA += c0 * s0 + c1 * s1;
                pB += c2 * s0 + c3 * s1;
                qA += c0 * d0 + c1 * d1;
                qB += c2 * d0 + c3 * d1;
            }
            if (gr0 < NN) *(float2*)(out + (size_t)gr0 * 128 + gc) = make_float2(c0, c1);
            if (gr1 < NN) *(float2*)(out + (size_t)gr1 * 128 + gc) = make_float2(c2, c3);
        }
        if (MODE >= 1) {
            pA += __shfl_xor_sync(0xffffffffu, pA, 1); pA += __shfl_xor_sync(0xffffffffu, pA, 2);
            pB += __shfl_xor_sync(0xffffffffu, pB, 1); pB += __shfl_xor_sync(0xffffffffu, pB, 2);
            qA += __shfl_xor_sync(0xffffffffu, qA, 1); qA += __shfl_xor_sync(0xffffffffu, qA, 2);
            qB += __shfl_xor_sync(0xffffffffu, qB, 1); qB += __shfl_xor_sync(0xffffffffu, qB, 2);
            if (kq == 0) {
                int rb = RM + mi * 16 + r_low;
                atomicAdd(&red[half * 256 + rb], pA);
                atomicAdd(&red[half * 256 + rb + 8], pB);
                atomicAdd(&red[half * 256 + 128 + rb], qA);
                atomicAdd(&red[half * 256 + 128 + rb + 8], qB);
            }
        }
    }
    if (MODE >= 1) {
        __syncthreads();
        if (tid < 128) {
            int gr = m0 + tid;
            if (gr < NN) {
                if (MODE == 1)
                    attn_out[gr] = make_float4(red[tid], red[128 + tid], 0.f, 0.f);
                else
                    attn_out[gr] = make_float4(red[tid], red[128 + tid], red[256 + tid], red[384 + tid]);
            }
        }
    }
}

// ---------------- single-pass online-softmax aggregation --------------------
template <bool USE_S, bool RELU, bool RESID>
__global__ void agg128_k(const float* __restrict__ t, const float* __restrict__ bias,
                         const float* __restrict__ resid, float* __restrict__ out)
{
    int n = (blockIdx.x * blockDim.x + threadIdx.x) >> 5;
    int lane = threadIdx.x & 31;
    if (n >= NN) return;
    int beg = g_rowptr[n], end = g_rowptr[n + 1];
    const float* attn_f = (const float*)g_attn;
    float asn = attn_f[4 * n], adn = attn_f[4 * n + 1];
    float m = -1e30f, den = 0.f, ss = 0.f;
    float a0 = 0.f, a1 = 0.f, a2 = 0.f, a3 = 0.f;
    for (int i = beg; i < end; i++) {
        float4 pk = g_pack[i];
        int s = __float_as_int(pk.x);
        float sv = USE_S ? pk.y : 0.f;
        float a = lrelu(attn_f[4 * s] + adn + sv);
        float mn = fmaxf(m, a);
        float c = __expf(m - mn);
        float w = __expf(a - mn);
        den = den * c + w;
        float4 hv = *(const float4*)(t + (size_t)s * 128 + lane * 4);
        a0 = a0 * c + w * hv.x; a1 = a1 * c + w * hv.y;
        a2 = a2 * c + w * hv.z; a3 = a3 * c + w * hv.w;
        if (USE_S) ss += sv;
        m = mn;
    }
    int deg = end - beg;
    float aself = lrelu(asn + adn + (USE_S ? ss / (float)(deg > 0 ? deg : 1) : 0.f));
    {
        float mn = fmaxf(m, aself);
        float c = __expf(m - mn);
        float w = __expf(aself - mn);
        den = den * c + w;
        float4 hv = *(const float4*)(t + (size_t)n * 128 + lane * 4);
        a0 = a0 * c + w * hv.x; a1 = a1 * c + w * hv.y;
        a2 = a2 * c + w * hv.z; a3 = a3 * c + w * hv.w;
    }
    float inv = 1.f / (den + 1e-16f);
    float4 bv = *(const float4*)(bias + lane * 4);
    float o0 = a0 * inv + bv.x, o1 = a1 * inv + bv.y;
    float o2 = a2 * inv + bv.z, o3 = a3 * inv + bv.w;
    if (RELU) { o0 = fmaxf(o0, 0.f); o1 = fmaxf(o1, 0.f); o2 = fmaxf(o2, 0.f); o3 = fmaxf(o3, 0.f); }
    if (RESID) {
        float4 rv = *(const float4*)(resid + (size_t)n * 128 + lane * 4);
        o0 += rv.x; o1 += rv.y; o2 += rv.z; o3 += rv.w;
    }
    *(float4*)(out + (size_t)n * 128 + lane * 4) = make_float4(o0, o1, o2, o3);
}

// fused mu/ls aggregation: lanes 0-15 -> mu (cols 0-63), 16-31 -> ls (64-127)
__global__ void agg_muls_k(const float* __restrict__ t,
                           const float* __restrict__ bmu, const float* __restrict__ bls,
                           float* __restrict__ out)
{
    int n = (blockIdx.x * blockDim.x + threadIdx.x) >> 5;
    int lane = threadIdx.x & 31;
    if (n >= NN) return;
    int half = lane >> 4, cl = lane & 15;
    int beg = g_rowptr[n], end = g_rowptr[n + 1];
    float4 at_n = g_attn[n];
    float asn = half ? at_n.z : at_n.x;
    float adn = half ? at_n.w : at_n.y;
    float m = -1e30f, den = 0.f, ss = 0.f;
    float a0 = 0.f, a1 = 0.f, a2 = 0.f, a3 = 0.f;
    for (int i = beg; i < end; i++) {
        float4 pk = g_pack[i];
        int s = __float_as_int(pk.x);
        float sv = half ? pk.w : pk.z;
        float4 as4 = g_attn[s];
        float a = lrelu((half ? as4.z : as4.x) + adn + sv);
        float mn = fmaxf(m, a);
        float c = __expf(m - mn);
        float w = __expf(a - mn);
        den = den * c + w;
        float4 hv = *(const float4*)(t + (size_t)s * 128 + lane * 4);
        a0 = a0 * c + w * hv.x; a1 = a1 * c + w * hv.y;
        a2 = a2 * c + w * hv.z; a3 = a3 * c + w * hv.w;
        ss += sv;
        m = mn;
    }
    int deg = end - beg;
    float aself = lrelu(asn + adn + ss / (float)(deg > 0 ? deg : 1));
    {
        float mn = fmaxf(m, aself);
        float c = __expf(m - mn);
        float w = __expf(aself - mn);
        den = den * c + w;
        float4 hv = *(const float4*)(t + (size_t)n * 128 + lane * 4);
        a0 = a0 * c + w * hv.x; a1 = a1 * c + w * hv.y;
        a2 = a2 * c + w * hv.z; a3 = a3 * c + w * hv.w;
    }
    float inv = 1.f / (den + 1e-16f);
    const float* bb = half ? bls : bmu;
    float4 bv = *(const float4*)(bb + cl * 4);
    float4 o = make_float4(a0 * inv + bv.x, a1 * inv + bv.y, a2 * inv + bv.z, a3 * inv + bv.w);
    float* obase = out + (half ? (size_t)NN * 64 : (size_t)0) + (size_t)n * 64 + cl * 4;
    *(float4*)obase = o;
}

// ---------------- launch ----------------------------------------------------
extern "C" void kernel_launch(void* const* d_in, const int* in_sizes, int n_in,
                              void* d_out, int out_size) {
    const float* x     = (const float*)d_in[0];
    const int*   ei    = (const int*)d_in[1];
    const int*   src   = ei;
    const int*   dst   = ei + NE;
    const float* eattr = (const float*)d_in[2];
    const float* W1    = (const float*)d_in[3];
    const float* a1s   = (const float*)d_in[4];
    const float* a1d   = (const float*)d_in[5];
    const float* b1    = (const float*)d_in[6];
    const float* W2    = (const float*)d_in[7];
    const float* a2s   = (const float*)d_in[8];
    const float* a2d   = (const float*)d_in[9];
    const float* b2    = (const float*)d_in[10];
    const float* We2   = (const float*)d_in[11];
    const float* ae2   = (const float*)d_in[12];
    const float* Wr    = (const float*)d_in[13];
    const float* br    = (const float*)d_in[14];
    const float* Wmu   = (const float*)d_in[15];
    const float* amus  = (const float*)d_in[16];
    const float* amud  = (const float*)d_in[17];
    const float* bmu   = (const float*)d_in[18];
    const float* Wemu  = (const float*)d_in[19];
    const float* aemu  = (const float*)d_in[20];
    const float* Wls   = (const float*)d_in[21];
    const float* alss  = (const float*)d_in[22];
    const float* alsd  = (const float*)d_in[23];
    const float* bls   = (const float*)d_in[24];
    const float* Wels  = (const float*)d_in[25];
    const float* aels  = (const float*)d_in[26];
    float* out = (float*)d_out;

    float *A_, *B_, *C_;
    float4* AT_;
    cudaGetSymbolAddress((void**)&A_, g_A);
    cudaGetSymbolAddress((void**)&B_, g_B);
    cudaGetSymbolAddress((void**)&C_, g_C);
    cudaGetSymbolAddress((void**)&AT_, g_attn);

    const int SMEMSZ = SM_FLOATS * 4;   // 140288 B
    cudaFuncSetAttribute(gemm_mma<0>, cudaFuncAttributeMaxDynamicSharedMemorySize, SMEMSZ);
    cudaFuncSetAttribute(gemm_mma<1>, cudaFuncAttributeMaxDynamicSharedMemorySize, SMEMSZ);
    cudaFuncSetAttribute(gemm_mma<2>, cudaFuncAttributeMaxDynamicSharedMemorySize, SMEMSZ);

    const int NB_SCAN = (NN + 1023) / 1024;
    const int GRID_N  = (NN + 255) / 256;
    const int GRID_E  = (NE + 255) / 256;
    const int GRID_W  = 12500;                  // N warps @ 8 warps/block
    const int GRID_G  = (NN + 127) / 128;       // 782 tiles

    // CSR build + per-edge scalars
    zero_counts_k<<<GRID_N, 256>>>();
    count_k<<<GRID_E, 256>>>(dst);
    scan1_k<<<NB_SCAN, 1024>>>();
    scan2_k<<<1, 128>>>(NB_SCAN);
    scan3_k<<<GRID_N, 256>>>();
    wvec_k<<<1, 512>>>(We2, ae2, 128, 0);
    wvec_k<<<1, 512>>>(Wemu, aemu, 64, 1);
    wvec_k<<<1, 512>>>(Wels, aels, 64, 2);
    scatter_k<<<GRID_E, 256>>>(src, dst, eattr);

    // conv1: t1 = x@W1 (+attn), h1 = relu(gat1)
    gemm_mma<1><<<GRID_G, 256, SMEMSZ>>>(x, W1, nullptr, nullptr, a1s, a1d, nullptr, nullptr, A_, AT_);
    agg128_k<false, true, false><<<GRID_W, 256>>>(A_, b1, nullptr, B_);

    // residual: r = x@Wr + br
    gemm_mma<0><<<GRID_G, 256, SMEMSZ>>>(x, Wr, nullptr, br, nullptr, nullptr, nullptr, nullptr, C_, nullptr);

    // conv2: t2 = h1@W2 (+attn), h = relu(gat2) + r
    gemm_mma<1><<<GRID_G, 256, SMEMSZ>>>(B_, W2, nullptr, nullptr, a2s, a2d, nullptr, nullptr, A_, AT_);
    agg128_k<true, true, true><<<GRID_W, 256>>>(A_, b2, C_, C_);

    // conv_mu + conv_logstd fused
    gemm_mma<2><<<GRID_G, 256, SMEMSZ>>>(C_, Wmu, Wls, nullptr, amus, amud, alss, alsd, A_, AT_);
    agg_muls_k<<<GRID_W, 256>>>(A_, bmu, bls, out);
}